// round 15
// baseline (speedup 1.0000x reference)
#include <cuda_runtime.h>
#include <cuda_bf16.h>
#include <math.h>
#include <stdint.h>

// Problem constants
#define BB 2048
#define DD 256
#define KK 256
#define NCC 64
#define FF 512
#define EPSf 0.001f
#define TAU_MINf 0.01f
#define ISPLIT 9
#define QLSEG 3

// ---------------- device scratch (static only) ----------------
__device__ float g_r2[BB];
__device__ float g_tau[BB];
__device__ float g_lam[BB];
__device__ float g_qp[QLSEG * BB * KK];               // q_lin partials
__device__ float g_bsum[KK];                          // bqz + bqf
__device__ float g_part[ISPLIT * BB * KK];            // quad partials
__device__ float g_cqT[KK * NCC];                     // chart_queries^T
__device__ __nv_bfloat16 g_Bbf[(size_t)KK * DD * DD]; // symmetrized G bf16

// pair table for conv (upper-triangular 4x4 tile pairs incl diag)
__device__ const int PTI[10] = {0,0,0,0,1,1,1,2,2,3};
__device__ const int PTJ[10] = {0,1,2,3,1,2,3,2,3,3};

// quad split boundaries balanced by kc-weight (w = 4 - skipped kc per chunk);
// per-split weight 239-245 out of total 2176.
__device__ const int SPLITB[10] = {0,61,125,195,266,329,399,471,543,640};

// ---------------- helpers (baseline PTX, sm_80-class) ----------------
__device__ __forceinline__ uint32_t smem_u32(const void* p) {
    uint32_t a;
    asm("{ .reg .u64 t; cvta.to.shared.u64 t, %1; cvt.u32.u64 %0, t; }"
        : "=r"(a) : "l"(p));
    return a;
}
__device__ __forceinline__ uint32_t swz(uint32_t b) { return b ^ ((b >> 3) & 0x70); }

__device__ __forceinline__ void cp_async16(uint32_t dst, const void* src) {
    asm volatile("cp.async.cg.shared.global [%0], [%1], 16;" :: "r"(dst), "l"(src) : "memory");
}
__device__ __forceinline__ void cp_commit() {
    asm volatile("cp.async.commit_group;" ::: "memory");
}
__device__ __forceinline__ void cp_wait2() {
    asm volatile("cp.async.wait_group 2;" ::: "memory");
}
__device__ __forceinline__ void ldsm_x4(uint32_t& r0, uint32_t& r1, uint32_t& r2,
                                        uint32_t& r3, uint32_t a) {
    asm volatile("ldmatrix.sync.aligned.m8n8.x4.shared.b16 {%0,%1,%2,%3}, [%4];"
                 : "=r"(r0), "=r"(r1), "=r"(r2), "=r"(r3) : "r"(a));
}
__device__ __forceinline__ void mma16816(float* d, const uint32_t* a, const uint32_t* b) {
    asm volatile(
        "mma.sync.aligned.m16n8k16.row.col.f32.bf16.bf16.f32 "
        "{%0,%1,%2,%3}, {%4,%5,%6,%7}, {%8,%9}, {%0,%1,%2,%3};"
        : "+f"(d[0]), "+f"(d[1]), "+f"(d[2]), "+f"(d[3])
        : "r"(a[0]), "r"(a[1]), "r"(a[2]), "r"(a[3]), "r"(b[0]), "r"(b[1]));
}
__device__ __forceinline__ uint32_t hmul2u(uint32_t a, uint32_t b) {
    __nv_bfloat162 r = __hmul2(*(__nv_bfloat162*)&a, *(__nv_bfloat162*)&b);
    return *(uint32_t*)&r;
}

// Upper-pair chunk decode: c in [0,640) -> (i in [0,256), jc in [i>>6, 4))
__device__ __forceinline__ void dec_chunk(int c, int& i, int& jc) {
    if (c < 256)      { i = c >> 2;                jc = c & 3; }
    else if (c < 448) { int t = c - 256; int q = t / 3; i = 64 + q;  jc = 1 + (t - 3 * q); }
    else if (c < 576) { int t = c - 448;           i = 128 + (t >> 1); jc = 2 + (t & 1); }
    else              { i = 192 + (c - 576);       jc = 3; }
}

// ================= fused prep kernel: conv | qlin | stats | tr =================
// 3264 CTAs: in each group of 51, blocks 0-39 are conv (2560 total),
// 40-50 are "other" (704 total: 384 qlin, 256 stats, 64 tr).
__global__ __launch_bounds__(256) void k_prep(
    const float* __restrict__ z, const float* __restrict__ feat,
    const float* __restrict__ Wqz, const float* __restrict__ Wqf,
    const float* __restrict__ G, const float* __restrict__ cq,
    const float* __restrict__ bqz, const float* __restrict__ bqf) {
    __shared__ __align__(16) float shf[4352];
    const int b = blockIdx.x;
    const int grp = b / 51, rr = b % 51;
    const int tid = threadIdx.x;

    if (rr < 40) {
        // ---------- conv role: symmetrize G -> bf16 B' ----------
        const int cidx = grp * 40 + rr;   // 0..2559
        const int p = cidx % 10;
        const int k = cidx / 10;
        const int ti = PTI[p], tj = PTJ[p];
        const float* Gk = G + (size_t)k * 65536;
        const bool diag = (ti == tj);
        // Issue BOTH tiles' loads up front (MLP 8) before any consumption.
        float4 tl[4];
#pragma unroll
        for (int t = 0; t < 4; t++) {
            int u = tid + t * 256;        // 1024 float4
            int r = u >> 4, m = u & 15;
            tl[t] = *(const float4*)(Gk + (size_t)(tj * 64 + r) * 256 + ti * 64 + 4 * m);
        }
        float4 upre[4];
        if (!diag) {
#pragma unroll
            for (int pass = 0; pass < 4; pass++) {
                int i = pass * 16 + (tid >> 4);
                int j0 = (tid & 15) * 4;
                upre[pass] = *(const float4*)(Gk + (size_t)(ti * 64 + i) * 256 + tj * 64 + j0);
            }
        }
#pragma unroll
        for (int t = 0; t < 4; t++) {
            int u = tid + t * 256;
            int r = u >> 4, m = u & 15;
            shf[r * 65 + 4 * m + 0] = tl[t].x; shf[r * 65 + 4 * m + 1] = tl[t].y;
            shf[r * 65 + 4 * m + 2] = tl[t].z; shf[r * 65 + 4 * m + 3] = tl[t].w;
        }
        __syncthreads();
#pragma unroll
        for (int pass = 0; pass < 4; pass++) {
            int i = pass * 16 + (tid >> 4);
            int j0 = (tid & 15) * 4;
            float o[4];
            if (diag) {
#pragma unroll
                for (int q = 0; q < 4; q++) {
                    int j = j0 + q;
                    float sum = shf[i * 65 + j] + shf[j * 65 + i];
                    o[q] = (j > i) ? sum : ((j == i) ? shf[i * 65 + i] : 0.f);
                }
            } else {
                float uq[4] = {upre[pass].x, upre[pass].y, upre[pass].z, upre[pass].w};
#pragma unroll
                for (int q = 0; q < 4; q++) o[q] = uq[q] + shf[(j0 + q) * 65 + i];
            }
            uint32_t b01, b23;
            asm("cvt.rn.bf16x2.f32 %0, %1, %2;" : "=r"(b01) : "f"(o[1]), "f"(o[0]));
            asm("cvt.rn.bf16x2.f32 %0, %1, %2;" : "=r"(b23) : "f"(o[3]), "f"(o[2]));
            *(uint2*)(g_Bbf + (size_t)k * 65536 + (size_t)(ti * 64 + i) * 256 + tj * 64 + j0)
                = make_uint2(b01, b23);
        }
        return;
    }

    const int o = grp * 11 + (rr - 40);   // 0..703

    if (o < 384) {
        // ---------- qlin role (fp32 SIMT, 3 contraction segments, LDS.128) ----------
        const int kt  = (o & 3) * 64;
        const int bt  = ((o >> 2) & 31) * 64;
        const int seg = o >> 7;
        const float* A  = (seg == 0) ? z   : feat;
        const float* Bm = (seg == 0) ? Wqz : Wqf;
        const int L   = (seg == 0) ? DD : FF;
        const int c00 = (seg == 2) ? 256 : 0;
        const int tm = tid & 15;
        const int tn = tid >> 4;
        float* As = shf;                  // [32][68]
        float* Bs = shf + 32 * 68;        // [32][68]
        float acc[4][4] = {};
        for (int c0 = c00; c0 < c00 + 256; c0 += 32) {
            __syncthreads();
#pragma unroll
            for (int t = 0; t < 2; t++) {
                int idx = tid + t * 256;
                int r = idx >> 3, m = idx & 7;
                float4 va = *(const float4*)(A + (size_t)(bt + r) * L + c0 + 4 * m);
                As[(4 * m + 0) * 68 + r] = va.x; As[(4 * m + 1) * 68 + r] = va.y;
                As[(4 * m + 2) * 68 + r] = va.z; As[(4 * m + 3) * 68 + r] = va.w;
                float4 vb = *(const float4*)(Bm + (size_t)(kt + r) * L + c0 + 4 * m);
                Bs[(4 * m + 0) * 68 + r] = vb.x; Bs[(4 * m + 1) * 68 + r] = vb.y;
                Bs[(4 * m + 2) * 68 + r] = vb.z; Bs[(4 * m + 3) * 68 + r] = vb.w;
            }
            __syncthreads();
#pragma unroll
            for (int kk = 0; kk < 32; kk++) {
                float4 a4 = *(const float4*)(As + kk * 68 + tm * 4);
                float4 b4 = *(const float4*)(Bs + kk * 68 + tn * 4);
                float a[4] = {a4.x, a4.y, a4.z, a4.w};
                float bb[4] = {b4.x, b4.y, b4.z, b4.w};
#pragma unroll
                for (int i = 0; i < 4; i++)
#pragma unroll
                    for (int j = 0; j < 4; j++)
                        acc[i][j] = fmaf(a[i], bb[j], acc[i][j]);
            }
        }
        float* outp = g_qp + (size_t)seg * BB * KK;
#pragma unroll
        for (int i = 0; i < 4; i++) {
            int br = bt + 4 * tm + i;
#pragma unroll
            for (int j = 0; j < 4; j++)
                outp[(size_t)br * KK + (kt + 4 * tn + j)] = acc[i][j];
        }
        return;
    }

    if (o < 640) {
        // ---------- stats role: 8 rows per CTA ----------
        const int sidx = o - 384;         // 0..255
        int warp = sidx * 8 + (tid >> 5);
        int lane = tid & 31;
        const float* zr = z + (size_t)warp * DD;
        float s = 0.f;
#pragma unroll
        for (int d = lane; d < DD; d += 32) { float v = zr[d]; s = fmaf(v, v, s); }
#pragma unroll
        for (int of = 16; of; of >>= 1) s += __shfl_xor_sync(0xffffffffu, s, of);
        if (lane == 0) {
            float r2 = s;
            g_r2[warp] = r2;
            g_tau[warp] = fmaxf(16.0f * fmaxf(1.0f - r2, 0.001f) * 0.5f, TAU_MINf);
            float r2c = fminf(r2, 1.0f - EPSf);
            g_lam[warp] = 2.0f / (1.0f - r2c + EPSf);
        }
        return;
    }

    // ---------- tr role: transpose cq + bias sum ----------
    {
        const int tidx = o - 640;         // 0..63
        int idx = tidx * 256 + tid;       // 0..16383
        int k = idx / NCC, c = idx % NCC;
        g_cqT[idx] = cq[(size_t)c * KK + k];
        if (idx < KK) g_bsum[idx] = bqz[idx] + bqf[idx];
    }
}

extern __shared__ __align__(1024) char qsm[];

// ---------------- quad via HMMA, symmetrized upper chunks + kc-skip ----------------
// CTA tile 256(batch) x 128(Gamma), 8 warps 4(M) x 2(N), warp tile 64x64.
// 640 upper (i,jc) chunks; diagonal-tile chunks skip kc blocks that are
// entirely in the exact-zero triangle (bitwise-identical results).
// Splits balanced by kc-weight (SPLITB) -> 144 CTAs, 1 wave.
#define ZROWB 528
#define QB_OFF 135168                     // 256 * 528
#define BSZ 16384
#define QSM_TOTAL (QB_OFF + 4 * BSZ)      // 200704

__device__ __forceinline__ void q_copy_b(uint32_t base, int kt, int cglob,
                                         int stage, int tid) {
    int i, jc; dec_chunk(cglob, i, jc);
    uint32_t dst = base + QB_OFF + stage * BSZ;
    const __nv_bfloat16* s0 = g_Bbf + (size_t)kt * 65536 + i * 256 + jc * 64;
#pragma unroll
    for (int q = 0; q < 4; q++) {
        int u = tid + q * 256;
        int r = u >> 3, m = u & 7;
        cp_async16(dst + swz((uint32_t)(r * 128 + m * 16)), s0 + (size_t)r * 65536 + m * 8);
    }
}

__global__ __launch_bounds__(256, 1) void k_quad(const float* __restrict__ z) {
    uint32_t base = smem_u32(qsm);
    const int tid = threadIdx.x;
    const int wid = tid >> 5, lane = tid & 31;
    const int kt = blockIdx.x * 128;      // Gamma tile
    const int bt = blockIdx.y * 256;      // batch tile
    const int split = blockIdx.z;

    // weight-balanced chunk range for this split
    const int cs = SPLITB[split];
    const int ce = SPLITB[split + 1];
    const int nch = ce - cs;

    // prologue B prefetch FIRST so pipeline fill overlaps the z-tile load
    for (int p = 0; p < 3; p++) { q_copy_b(base, kt, cs + p, p, tid); cp_commit(); }

    // z tile -> bf16 SMEM [256 rows][264 bf16, 528B stride]
#pragma unroll
    for (int t = 0; t < 32; t++) {
        int u = tid + t * 256;
        int r = u >> 5, m = u & 31;
        const float4* s = (const float4*)(z + (size_t)(bt + r) * DD + 8 * m);
        float4 v0 = s[0], v1 = s[1];
        uint32_t c0, c1, c2, c3;
        asm("cvt.rn.bf16x2.f32 %0, %1, %2;" : "=r"(c0) : "f"(v0.y), "f"(v0.x));
        asm("cvt.rn.bf16x2.f32 %0, %1, %2;" : "=r"(c1) : "f"(v0.w), "f"(v0.z));
        asm("cvt.rn.bf16x2.f32 %0, %1, %2;" : "=r"(c2) : "f"(v1.y), "f"(v1.x));
        asm("cvt.rn.bf16x2.f32 %0, %1, %2;" : "=r"(c3) : "f"(v1.w), "f"(v1.z));
        *(uint4*)(qsm + r * ZROWB + 16 * m) = make_uint4(c0, c1, c2, c3);
    }
    __syncthreads();

    const int wm = wid & 3;
    const int wn = wid >> 2;

    int zoff_lo[4], zoff_hi[4];
#pragma unroll
    for (int mi = 0; mi < 4; mi++) {
        int row = wm * 64 + mi * 16 + (lane >> 2);
        zoff_lo[mi] = row * ZROWB;
        zoff_hi[mi] = (row + 8) * ZROWB;
    }
    const int jlane = (lane & 3) * 4;

    uint32_t brb[4], bmask[4];
#pragma unroll
    for (int p = 0; p < 4; p++) {
        int row = wn * 64 + p * 16 + (lane & 7) + ((lane >> 4) & 1) * 8;
        brb[p] = (uint32_t)(row * 128);
        bmask[p] = (uint32_t)((row & 7) << 4);
    }
    const uint32_t bcol0 = (uint32_t)(((lane >> 3) & 1) * 16);

    float acc[4][8][4] = {};

#pragma unroll 1
    for (int l = 0; l < nch; l++) {
        cp_wait2();
        __syncthreads();
        if (l + 3 < nch) q_copy_b(base, kt, cs + l + 3, (l + 3) & 3, tid);
        cp_commit();

        int ci, cjc; dec_chunk(cs + l, ci, cjc);
        // kc blocks entirely inside the zero triangle of a diagonal tile are
        // exact no-ops (B' stores 0.0f there) -> skip them, bitwise identical.
        const int kc0 = (cjc == (ci >> 6)) ? ((ci & 63) >> 4) : 0;
        const int icol = ci * 2;          // byte offset of z_i
        uint32_t zi_lo[4], zi_hi[4];
#pragma unroll
        for (int mi = 0; mi < 4; mi++) {
            __nv_bfloat162 d2 = __bfloat162bfloat162(*(__nv_bfloat16*)(qsm + zoff_lo[mi] + icol));
            zi_lo[mi] = *(uint32_t*)&d2;
            d2 = __bfloat162bfloat162(*(__nv_bfloat16*)(qsm + zoff_hi[mi] + icol));
            zi_hi[mi] = *(uint32_t*)&d2;
        }
        const int jb2 = cjc * 128;        // byte offset of j-block
        const uint32_t bbase = base + QB_OFF + (l & 3) * BSZ;

#pragma unroll 1
        for (int kc = kc0; kc < 4; kc++) {
            uint32_t bfr[4][4];
#pragma unroll
            for (int p = 0; p < 4; p++)
                ldsm_x4(bfr[p][0], bfr[p][1], bfr[p][2], bfr[p][3],
                        bbase + brb[p] + ((bcol0 + kc * 32) ^ bmask[p]));
            uint32_t af[4][4];
#pragma unroll
            for (int mi = 0; mi < 4; mi++) {
                int col = jb2 + kc * 32 + jlane;
                uint32_t jlo0 = *(uint32_t*)(qsm + zoff_lo[mi] + col);
                uint32_t jhi0 = *(uint32_t*)(qsm + zoff_hi[mi] + col);
                uint32_t jlo8 = *(uint32_t*)(qsm + zoff_lo[mi] + col + 16);
                uint32_t jhi8 = *(uint32_t*)(qsm + zoff_hi[mi] + col + 16);
                af[mi][0] = hmul2u(jlo0, zi_lo[mi]);
                af[mi][1] = hmul2u(jhi0, zi_hi[mi]);
                af[mi][2] = hmul2u(jlo8, zi_lo[mi]);
                af[mi][3] = hmul2u(jhi8, zi_hi[mi]);
            }
#pragma unroll
            for (int mi = 0; mi < 4; mi++)
#pragma unroll
                for (int ni = 0; ni < 8; ni++) {
                    uint32_t bb[2];
                    bb[0] = bfr[ni >> 1][(ni & 1) * 2 + 0];
                    bb[1] = bfr[ni >> 1][(ni & 1) * 2 + 1];
                    mma16816(acc[mi][ni], af[mi], bb);
                }
        }
    }

    // epilogue: partials [split][b][k]
    {
        float* outp = g_part + (size_t)split * BB * KK
                    + (size_t)(bt + wm * 64) * KK + kt + wn * 64;
        int r0 = lane >> 2, c0 = (lane & 3) * 2;
#pragma unroll
        for (int mi = 0; mi < 4; mi++)
#pragma unroll
            for (int ni = 0; ni < 8; ni++) {
                float* p0 = outp + (size_t)(mi * 16 + r0) * KK + ni * 8 + c0;
                *(float2*)p0 = make_float2(acc[mi][ni][0], acc[mi][ni][1]);
                *(float2*)(p0 + 8 * KK) = make_float2(acc[mi][ni][2], acc[mi][ni][3]);
            }
    }
}

// ---------------- scores + softmax + argmax (4 rows per 256-thread CTA) ----------------
__global__ __launch_bounds__(256) void k_score(
    const float* __restrict__ z, float* __restrict__ out, int out_size) {
    __shared__ float zsm[4][256];
    __shared__ float qsm2[4][256];
    __shared__ float sc[4][64];
    __shared__ float ex[4][64];
    const int row = threadIdx.x >> 6;     // 0..3
    const int c   = threadIdx.x & 63;
    const int b = blockIdx.x * 4 + row;
#pragma unroll
    for (int k = c; k < 256; k += 64) {
        zsm[row][k] = z[(size_t)b * DD + k];
        size_t off = (size_t)b * KK + k;
        float qv = g_bsum[k];
#pragma unroll
        for (int s = 0; s < QLSEG; s++)
            qv += g_qp[(size_t)s * BB * KK + off];
#pragma unroll
        for (int s = 0; s < ISPLIT; s++)
            qv += g_part[(size_t)s * BB * KK + off];
        qsm2[row][k] = qv;
    }
    __syncthreads();
    float dzc = 0.f, fs = 0.f, csq = 0.f;
#pragma unroll 8
    for (int k = 0; k < 256; k++) {
        float v = g_cqT[k * NCC + c];
        dzc = fmaf(zsm[row][k], v, dzc);
        fs  = fmaf(qsm2[row][k], v, fs);
        csq = fmaf(v, v, csq);
    }
    float r2 = g_r2[b], tau = g_tau[b], lam = g_lam[b];
    float dist_sq = r2 + csq - 2.0f * dzc;
    float denom = (1.0f - r2) * (1.0f - csq);
    float arg = 1.0f + 2.0f * dist_sq / (denom + EPSf);
    float dist = acoshf(fmaxf(arg, 1.0f + EPSf));
    float score = -dist / tau + 0.1f * fs / (lam * tau);

    sc[row][c] = score;
    __syncthreads();
    float m = sc[row][0];
#pragma unroll
    for (int j = 1; j < 64; j++) m = fmaxf(m, sc[row][j]);
    float e = expf(score - m);
    ex[row][c] = e;
    __syncthreads();
    float s = 0.f;
#pragma unroll
    for (int j = 0; j < 64; j++) s += ex[row][j];

    if (out_size >= BB * NCC)
        out[(size_t)b * NCC + c] = e / s;

    if (c == 0) {
        int bi = 0; float bv = sc[row][0];
#pragma unroll
        for (int j = 1; j < 64; j++)
            if (sc[row][j] > bv) { bv = sc[row][j]; bi = j; }
        if (out_size >= BB * NCC + BB)      out[BB * NCC + b] = (float)bi;
        else if (out_size == BB)            out[b] = (float)bi;
    }
}

// ---------------- launch ----------------
extern "C" void kernel_launch(void* const* d_in, const int* in_sizes, int n_in,
                              void* d_out, int out_size) {
    const float* z    = (const float*)d_in[0];
    const float* feat = (const float*)d_in[1];
    const float* Wqz  = (const float*)d_in[2];
    const float* bqz  = (const float*)d_in[3];
    const float* Wqf  = (const float*)d_in[4];
    const float* bqf  = (const float*)d_in[5];
    const float* G    = (const float*)d_in[6];
    const float* cq   = (const float*)d_in[7];
    float* out = (float*)d_out;

    k_prep<<<3264, 256>>>(z, feat, Wqz, Wqf, G, cq, bqz, bqf);

    cudaFuncSetAttribute((const void*)k_quad,
                         cudaFuncAttributeMaxDynamicSharedMemorySize, QSM_TOTAL);
    k_quad<<<dim3(KK / 128, BB / 256, ISPLIT), 256, QSM_TOTAL>>>(z);

    k_score<<<BB / 4, 256>>>(z, out, out_size);
}

// round 16
// speedup vs baseline: 1.0451x; 1.0451x over previous
#include <cuda_runtime.h>
#include <cuda_bf16.h>
#include <math.h>
#include <stdint.h>

// Problem constants
#define BB 2048
#define DD 256
#define KK 256
#define NCC 64
#define FF 512
#define EPSf 0.001f
#define TAU_MINf 0.01f
#define ISPLIT 9
#define QLSEG 3

// ---------------- device scratch (static only) ----------------
__device__ float g_r2[BB];
__device__ float g_tau[BB];
__device__ float g_lam[BB];
__device__ float g_qp[QLSEG * BB * KK];               // q_lin partials
__device__ float g_bsum[KK];                          // bqz + bqf
__device__ float g_part[ISPLIT * BB * KK];            // quad partials
__device__ float g_cqT[KK * NCC];                     // chart_queries^T
__device__ __nv_bfloat16 g_Bbf[(size_t)KK * DD * DD]; // symmetrized G bf16

// pair table for conv (upper-triangular 4x4 tile pairs incl diag)
__device__ const int PTI[10] = {0,0,0,0,1,1,1,2,2,3};
__device__ const int PTJ[10] = {0,1,2,3,1,2,3,2,3,3};

// quad split boundaries balanced by kc-weight (w = 4 - skipped kc per chunk);
// per-split weight 239-245 out of total 2176.
__device__ const int SPLITB[10] = {0,61,125,195,266,329,399,471,543,640};

// ---------------- helpers (baseline PTX, sm_80-class) ----------------
__device__ __forceinline__ uint32_t smem_u32(const void* p) {
    uint32_t a;
    asm("{ .reg .u64 t; cvta.to.shared.u64 t, %1; cvt.u32.u64 %0, t; }"
        : "=r"(a) : "l"(p));
    return a;
}
__device__ __forceinline__ uint32_t swz(uint32_t b) { return b ^ ((b >> 3) & 0x70); }

__device__ __forceinline__ void cp_async16(uint32_t dst, const void* src) {
    asm volatile("cp.async.cg.shared.global [%0], [%1], 16;" :: "r"(dst), "l"(src) : "memory");
}
__device__ __forceinline__ void cp_commit() {
    asm volatile("cp.async.commit_group;" ::: "memory");
}
__device__ __forceinline__ void cp_wait2() {
    asm volatile("cp.async.wait_group 2;" ::: "memory");
}
__device__ __forceinline__ void ldsm_x4(uint32_t& r0, uint32_t& r1, uint32_t& r2,
                                        uint32_t& r3, uint32_t a) {
    asm volatile("ldmatrix.sync.aligned.m8n8.x4.shared.b16 {%0,%1,%2,%3}, [%4];"
                 : "=r"(r0), "=r"(r1), "=r"(r2), "=r"(r3) : "r"(a));
}
__device__ __forceinline__ void mma16816(float* d, const uint32_t* a, const uint32_t* b) {
    asm volatile(
        "mma.sync.aligned.m16n8k16.row.col.f32.bf16.bf16.f32 "
        "{%0,%1,%2,%3}, {%4,%5,%6,%7}, {%8,%9}, {%0,%1,%2,%3};"
        : "+f"(d[0]), "+f"(d[1]), "+f"(d[2]), "+f"(d[3])
        : "r"(a[0]), "r"(a[1]), "r"(a[2]), "r"(a[3]), "r"(b[0]), "r"(b[1]));
}
__device__ __forceinline__ uint32_t hmul2u(uint32_t a, uint32_t b) {
    __nv_bfloat162 r = __hmul2(*(__nv_bfloat162*)&a, *(__nv_bfloat162*)&b);
    return *(uint32_t*)&r;
}

// Upper-pair chunk decode: c in [0,640) -> (i in [0,256), jc in [i>>6, 4))
__device__ __forceinline__ void dec_chunk(int c, int& i, int& jc) {
    if (c < 256)      { i = c >> 2;                jc = c & 3; }
    else if (c < 448) { int t = c - 256; int q = t / 3; i = 64 + q;  jc = 1 + (t - 3 * q); }
    else if (c < 576) { int t = c - 448;           i = 128 + (t >> 1); jc = 2 + (t & 1); }
    else              { i = 192 + (c - 576);       jc = 3; }
}

// ================= fused prep kernel: conv | qlin | stats | tr =================
// 3264 CTAs: in each group of 51, blocks 0-39 are conv (2560 total),
// 40-50 are "other" (704 total: 384 qlin, 256 stats, 64 tr).
__global__ __launch_bounds__(256) void k_prep(
    const float* __restrict__ z, const float* __restrict__ feat,
    const float* __restrict__ Wqz, const float* __restrict__ Wqf,
    const float* __restrict__ G, const float* __restrict__ cq,
    const float* __restrict__ bqz, const float* __restrict__ bqf) {
    __shared__ __align__(16) float shf[4352];
    const int b = blockIdx.x;
    const int grp = b / 51, rr = b % 51;
    const int tid = threadIdx.x;

    if (rr < 40) {
        // ---------- conv role: symmetrize G -> bf16 B' ----------
        const int cidx = grp * 40 + rr;   // 0..2559
        const int p = cidx % 10;
        const int k = cidx / 10;
        const int ti = PTI[p], tj = PTJ[p];
        const float* Gk = G + (size_t)k * 65536;
        const bool diag = (ti == tj);
        // Issue BOTH tiles' loads up front (MLP 8) before any consumption.
        float4 tl[4];
#pragma unroll
        for (int t = 0; t < 4; t++) {
            int u = tid + t * 256;        // 1024 float4
            int r = u >> 4, m = u & 15;
            tl[t] = *(const float4*)(Gk + (size_t)(tj * 64 + r) * 256 + ti * 64 + 4 * m);
        }
        float4 upre[4];
        if (!diag) {
#pragma unroll
            for (int pass = 0; pass < 4; pass++) {
                int i = pass * 16 + (tid >> 4);
                int j0 = (tid & 15) * 4;
                upre[pass] = *(const float4*)(Gk + (size_t)(ti * 64 + i) * 256 + tj * 64 + j0);
            }
        }
#pragma unroll
        for (int t = 0; t < 4; t++) {
            int u = tid + t * 256;
            int r = u >> 4, m = u & 15;
            shf[r * 65 + 4 * m + 0] = tl[t].x; shf[r * 65 + 4 * m + 1] = tl[t].y;
            shf[r * 65 + 4 * m + 2] = tl[t].z; shf[r * 65 + 4 * m + 3] = tl[t].w;
        }
        __syncthreads();
#pragma unroll
        for (int pass = 0; pass < 4; pass++) {
            int i = pass * 16 + (tid >> 4);
            int j0 = (tid & 15) * 4;
            float o[4];
            if (diag) {
#pragma unroll
                for (int q = 0; q < 4; q++) {
                    int j = j0 + q;
                    float sum = shf[i * 65 + j] + shf[j * 65 + i];
                    o[q] = (j > i) ? sum : ((j == i) ? shf[i * 65 + i] : 0.f);
                }
            } else {
                float uq[4] = {upre[pass].x, upre[pass].y, upre[pass].z, upre[pass].w};
#pragma unroll
                for (int q = 0; q < 4; q++) o[q] = uq[q] + shf[(j0 + q) * 65 + i];
            }
            uint32_t b01, b23;
            asm("cvt.rn.bf16x2.f32 %0, %1, %2;" : "=r"(b01) : "f"(o[1]), "f"(o[0]));
            asm("cvt.rn.bf16x2.f32 %0, %1, %2;" : "=r"(b23) : "f"(o[3]), "f"(o[2]));
            *(uint2*)(g_Bbf + (size_t)k * 65536 + (size_t)(ti * 64 + i) * 256 + tj * 64 + j0)
                = make_uint2(b01, b23);
        }
        return;
    }

    const int o = grp * 11 + (rr - 40);   // 0..703

    if (o < 384) {
        // ---------- qlin role (fp32 SIMT, 3 contraction segments, LDS.128) ----------
        const int kt  = (o & 3) * 64;
        const int bt  = ((o >> 2) & 31) * 64;
        const int seg = o >> 7;
        const float* A  = (seg == 0) ? z   : feat;
        const float* Bm = (seg == 0) ? Wqz : Wqf;
        const int L   = (seg == 0) ? DD : FF;
        const int c00 = (seg == 2) ? 256 : 0;
        const int tm = tid & 15;
        const int tn = tid >> 4;
        float* As = shf;                  // [32][68]
        float* Bs = shf + 32 * 68;        // [32][68]
        float acc[4][4] = {};
        for (int c0 = c00; c0 < c00 + 256; c0 += 32) {
            __syncthreads();
#pragma unroll
            for (int t = 0; t < 2; t++) {
                int idx = tid + t * 256;
                int r = idx >> 3, m = idx & 7;
                float4 va = *(const float4*)(A + (size_t)(bt + r) * L + c0 + 4 * m);
                As[(4 * m + 0) * 68 + r] = va.x; As[(4 * m + 1) * 68 + r] = va.y;
                As[(4 * m + 2) * 68 + r] = va.z; As[(4 * m + 3) * 68 + r] = va.w;
                float4 vb = *(const float4*)(Bm + (size_t)(kt + r) * L + c0 + 4 * m);
                Bs[(4 * m + 0) * 68 + r] = vb.x; Bs[(4 * m + 1) * 68 + r] = vb.y;
                Bs[(4 * m + 2) * 68 + r] = vb.z; Bs[(4 * m + 3) * 68 + r] = vb.w;
            }
            __syncthreads();
#pragma unroll
            for (int kk = 0; kk < 32; kk++) {
                float4 a4 = *(const float4*)(As + kk * 68 + tm * 4);
                float4 b4 = *(const float4*)(Bs + kk * 68 + tn * 4);
                float a[4] = {a4.x, a4.y, a4.z, a4.w};
                float bb[4] = {b4.x, b4.y, b4.z, b4.w};
#pragma unroll
                for (int i = 0; i < 4; i++)
#pragma unroll
                    for (int j = 0; j < 4; j++)
                        acc[i][j] = fmaf(a[i], bb[j], acc[i][j]);
            }
        }
        float* outp = g_qp + (size_t)seg * BB * KK;
#pragma unroll
        for (int i = 0; i < 4; i++) {
            int br = bt + 4 * tm + i;
#pragma unroll
            for (int j = 0; j < 4; j++)
                outp[(size_t)br * KK + (kt + 4 * tn + j)] = acc[i][j];
        }
        return;
    }

    if (o < 640) {
        // ---------- stats role: 8 rows per CTA ----------
        const int sidx = o - 384;         // 0..255
        int warp = sidx * 8 + (tid >> 5);
        int lane = tid & 31;
        const float* zr = z + (size_t)warp * DD;
        float s = 0.f;
#pragma unroll
        for (int d = lane; d < DD; d += 32) { float v = zr[d]; s = fmaf(v, v, s); }
#pragma unroll
        for (int of = 16; of; of >>= 1) s += __shfl_xor_sync(0xffffffffu, s, of);
        if (lane == 0) {
            float r2 = s;
            g_r2[warp] = r2;
            g_tau[warp] = fmaxf(16.0f * fmaxf(1.0f - r2, 0.001f) * 0.5f, TAU_MINf);
            float r2c = fminf(r2, 1.0f - EPSf);
            g_lam[warp] = 2.0f / (1.0f - r2c + EPSf);
        }
        return;
    }

    // ---------- tr role: transpose cq + bias sum ----------
    {
        const int tidx = o - 640;         // 0..63
        int idx = tidx * 256 + tid;       // 0..16383
        int k = idx / NCC, c = idx % NCC;
        g_cqT[idx] = cq[(size_t)c * KK + k];
        if (idx < KK) g_bsum[idx] = bqz[idx] + bqf[idx];
    }
}

extern __shared__ __align__(1024) char qsm[];

// ---------------- quad via HMMA, symmetrized upper chunks + kc-skip ----------------
// CTA tile 256(batch) x 128(Gamma), 8 warps 4(M) x 2(N), warp tile 64x64.
// 640 upper (i,jc) chunks; diagonal-tile chunks skip kc blocks that are
// entirely in the exact-zero triangle.  kc loop stays FULLY UNROLLED with a
// uniform predicated guard per block, preserving the pipelined schedule.
// Splits balanced by kc-weight (SPLITB) -> 144 CTAs, 1 wave.
#define ZROWB 528
#define QB_OFF 135168                     // 256 * 528
#define BSZ 16384
#define QSM_TOTAL (QB_OFF + 4 * BSZ)      // 200704

__device__ __forceinline__ void q_copy_b(uint32_t base, int kt, int cglob,
                                         int stage, int tid) {
    int i, jc; dec_chunk(cglob, i, jc);
    uint32_t dst = base + QB_OFF + stage * BSZ;
    const __nv_bfloat16* s0 = g_Bbf + (size_t)kt * 65536 + i * 256 + jc * 64;
#pragma unroll
    for (int q = 0; q < 4; q++) {
        int u = tid + q * 256;
        int r = u >> 3, m = u & 7;
        cp_async16(dst + swz((uint32_t)(r * 128 + m * 16)), s0 + (size_t)r * 65536 + m * 8);
    }
}

__global__ __launch_bounds__(256, 1) void k_quad(const float* __restrict__ z) {
    uint32_t base = smem_u32(qsm);
    const int tid = threadIdx.x;
    const int wid = tid >> 5, lane = tid & 31;
    const int kt = blockIdx.x * 128;      // Gamma tile
    const int bt = blockIdx.y * 256;      // batch tile
    const int split = blockIdx.z;

    // weight-balanced chunk range for this split
    const int cs = SPLITB[split];
    const int ce = SPLITB[split + 1];
    const int nch = ce - cs;

    // prologue B prefetch FIRST so pipeline fill overlaps the z-tile load
    for (int p = 0; p < 3; p++) { q_copy_b(base, kt, cs + p, p, tid); cp_commit(); }

    // z tile -> bf16 SMEM [256 rows][264 bf16, 528B stride]
#pragma unroll
    for (int t = 0; t < 32; t++) {
        int u = tid + t * 256;
        int r = u >> 5, m = u & 31;
        const float4* s = (const float4*)(z + (size_t)(bt + r) * DD + 8 * m);
        float4 v0 = s[0], v1 = s[1];
        uint32_t c0, c1, c2, c3;
        asm("cvt.rn.bf16x2.f32 %0, %1, %2;" : "=r"(c0) : "f"(v0.y), "f"(v0.x));
        asm("cvt.rn.bf16x2.f32 %0, %1, %2;" : "=r"(c1) : "f"(v0.w), "f"(v0.z));
        asm("cvt.rn.bf16x2.f32 %0, %1, %2;" : "=r"(c2) : "f"(v1.y), "f"(v1.x));
        asm("cvt.rn.bf16x2.f32 %0, %1, %2;" : "=r"(c3) : "f"(v1.w), "f"(v1.z));
        *(uint4*)(qsm + r * ZROWB + 16 * m) = make_uint4(c0, c1, c2, c3);
    }
    __syncthreads();

    const int wm = wid & 3;
    const int wn = wid >> 2;

    int zoff_lo[4], zoff_hi[4];
#pragma unroll
    for (int mi = 0; mi < 4; mi++) {
        int row = wm * 64 + mi * 16 + (lane >> 2);
        zoff_lo[mi] = row * ZROWB;
        zoff_hi[mi] = (row + 8) * ZROWB;
    }
    const int jlane = (lane & 3) * 4;

    uint32_t brb[4], bmask[4];
#pragma unroll
    for (int p = 0; p < 4; p++) {
        int row = wn * 64 + p * 16 + (lane & 7) + ((lane >> 4) & 1) * 8;
        brb[p] = (uint32_t)(row * 128);
        bmask[p] = (uint32_t)((row & 7) << 4);
    }
    const uint32_t bcol0 = (uint32_t)(((lane >> 3) & 1) * 16);

    float acc[4][8][4] = {};

#pragma unroll 1
    for (int l = 0; l < nch; l++) {
        cp_wait2();
        __syncthreads();
        if (l + 3 < nch) q_copy_b(base, kt, cs + l + 3, (l + 3) & 3, tid);
        cp_commit();

        int ci, cjc; dec_chunk(cs + l, ci, cjc);
        // kc blocks entirely inside the zero triangle of a diagonal tile are
        // exact no-ops (B' stores 0.0f there) -> skip via uniform guard.
        const int kc0 = (cjc == (ci >> 6)) ? ((ci & 63) >> 4) : 0;
        const int icol = ci * 2;          // byte offset of z_i
        uint32_t zi_lo[4], zi_hi[4];
#pragma unroll
        for (int mi = 0; mi < 4; mi++) {
            __nv_bfloat162 d2 = __bfloat162bfloat162(*(__nv_bfloat16*)(qsm + zoff_lo[mi] + icol));
            zi_lo[mi] = *(uint32_t*)&d2;
            d2 = __bfloat162bfloat162(*(__nv_bfloat16*)(qsm + zoff_hi[mi] + icol));
            zi_hi[mi] = *(uint32_t*)&d2;
        }
        const int jb2 = cjc * 128;        // byte offset of j-block
        const uint32_t bbase = base + QB_OFF + (l & 3) * BSZ;

#pragma unroll
        for (int kc = 0; kc < 4; kc++) {
            if (kc < kc0) continue;       // uniform guard; block stays statically scheduled
            uint32_t bfr[4][4];
#pragma unroll
            for (int p = 0; p < 4; p++)
                ldsm_x4(bfr[p][0], bfr[p][1], bfr[p][2], bfr[p][3],
                        bbase + brb[p] + ((bcol0 + kc * 32) ^ bmask[p]));
            uint32_t af[4][4];
#pragma unroll
            for (int mi = 0; mi < 4; mi++) {
                int col = jb2 + kc * 32 + jlane;
                uint32_t jlo0 = *(uint32_t*)(qsm + zoff_lo[mi] + col);
                uint32_t jhi0 = *(uint32_t*)(qsm + zoff_hi[mi] + col);
                uint32_t jlo8 = *(uint32_t*)(qsm + zoff_lo[mi] + col + 16);
                uint32_t jhi8 = *(uint32_t*)(qsm + zoff_hi[mi] + col + 16);
                af[mi][0] = hmul2u(jlo0, zi_lo[mi]);
                af[mi][1] = hmul2u(jhi0, zi_hi[mi]);
                af[mi][2] = hmul2u(jlo8, zi_lo[mi]);
                af[mi][3] = hmul2u(jhi8, zi_hi[mi]);
            }
#pragma unroll
            for (int mi = 0; mi < 4; mi++)
#pragma unroll
                for (int ni = 0; ni < 8; ni++) {
                    uint32_t bb[2];
                    bb[0] = bfr[ni >> 1][(ni & 1) * 2 + 0];
                    bb[1] = bfr[ni >> 1][(ni & 1) * 2 + 1];
                    mma16816(acc[mi][ni], af[mi], bb);
                }
        }
    }

    // epilogue: partials [split][b][k]
    {
        float* outp = g_part + (size_t)split * BB * KK
                    + (size_t)(bt + wm * 64) * KK + kt + wn * 64;
        int r0 = lane >> 2, c0 = (lane & 3) * 2;
#pragma unroll
        for (int mi = 0; mi < 4; mi++)
#pragma unroll
            for (int ni = 0; ni < 8; ni++) {
                float* p0 = outp + (size_t)(mi * 16 + r0) * KK + ni * 8 + c0;
                *(float2*)p0 = make_float2(acc[mi][ni][0], acc[mi][ni][1]);
                *(float2*)(p0 + 8 * KK) = make_float2(acc[mi][ni][2], acc[mi][ni][3]);
            }
    }
}

// ---------------- scores + softmax + argmax (4 rows per 256-thread CTA) ----------------
__global__ __launch_bounds__(256) void k_score(
    const float* __restrict__ z, float* __restrict__ out, int out_size) {
    __shared__ float zsm[4][256];
    __shared__ float qsm2[4][256];
    __shared__ float sc[4][64];
    __shared__ float ex[4][64];
    const int row = threadIdx.x >> 6;     // 0..3
    const int c   = threadIdx.x & 63;
    const int b = blockIdx.x * 4 + row;
#pragma unroll
    for (int k = c; k < 256; k += 64) {
        zsm[row][k] = z[(size_t)b * DD + k];
        size_t off = (size_t)b * KK + k;
        float qv = g_bsum[k];
#pragma unroll
        for (int s = 0; s < QLSEG; s++)
            qv += g_qp[(size_t)s * BB * KK + off];
#pragma unroll
        for (int s = 0; s < ISPLIT; s++)
            qv += g_part[(size_t)s * BB * KK + off];
        qsm2[row][k] = qv;
    }
    __syncthreads();
    float dzc = 0.f, fs = 0.f, csq = 0.f;
#pragma unroll 8
    for (int k = 0; k < 256; k++) {
        float v = g_cqT[k * NCC + c];
        dzc = fmaf(zsm[row][k], v, dzc);
        fs  = fmaf(qsm2[row][k], v, fs);
        csq = fmaf(v, v, csq);
    }
    float r2 = g_r2[b], tau = g_tau[b], lam = g_lam[b];
    float dist_sq = r2 + csq - 2.0f * dzc;
    float denom = (1.0f - r2) * (1.0f - csq);
    float arg = 1.0f + 2.0f * dist_sq / (denom + EPSf);
    float dist = acoshf(fmaxf(arg, 1.0f + EPSf));
    float score = -dist / tau + 0.1f * fs / (lam * tau);

    sc[row][c] = score;
    __syncthreads();
    float m = sc[row][0];
#pragma unroll
    for (int j = 1; j < 64; j++) m = fmaxf(m, sc[row][j]);
    float e = expf(score - m);
    ex[row][c] = e;
    __syncthreads();
    float s = 0.f;
#pragma unroll
    for (int j = 0; j < 64; j++) s += ex[row][j];

    if (out_size >= BB * NCC)
        out[(size_t)b * NCC + c] = e / s;

    if (c == 0) {
        int bi = 0; float bv = sc[row][0];
#pragma unroll
        for (int j = 1; j < 64; j++)
            if (sc[row][j] > bv) { bv = sc[row][j]; bi = j; }
        if (out_size >= BB * NCC + BB)      out[BB * NCC + b] = (float)bi;
        else if (out_size == BB)            out[b] = (float)bi;
    }
}

// ---------------- launch ----------------
extern "C" void kernel_launch(void* const* d_in, const int* in_sizes, int n_in,
                              void* d_out, int out_size) {
    const float* z    = (const float*)d_in[0];
    const float* feat = (const float*)d_in[1];
    const float* Wqz  = (const float*)d_in[2];
    const float* bqz  = (const float*)d_in[3];
    const float* Wqf  = (const float*)d_in[4];
    const float* bqf  = (const float*)d_in[5];
    const float* G    = (const float*)d_in[6];
    const float* cq   = (const float*)d_in[7];
    float* out = (float*)d_out;

    k_prep<<<3264, 256>>>(z, feat, Wqz, Wqf, G, cq, bqz, bqf);

    cudaFuncSetAttribute((const void*)k_quad,
                         cudaFuncAttributeMaxDynamicSharedMemorySize, QSM_TOTAL);
    k_quad<<<dim3(KK / 128, BB / 256, ISPLIT), 256, QSM_TOTAL>>>(z);

    k_score<<<BB / 4, 256>>>(z, out, out_size);
}